// round 2
// baseline (speedup 1.0000x reference)
#include <cuda_runtime.h>

#define N 8192
#define RANK 4
#define SCALING 2.0f   // ALPHA / RANK = 8 / 4
#define EPS 1e-5f
#define TPB 1024
#define V_PER_T (N / (TPB * 4))   // float4s per thread = 2

// Allocation-free scratch for the adapted affine vectors.
__device__ float g_scale[N];
__device__ float g_shift[N];

// ---------------------------------------------------------------------------
// Kernel 1: rank-4 low-rank diagonal -> per-feature scale/shift vectors.
// diag[i] = sum_r A[i,r] * B[r,i];  tiny (8192 threads), runs once per launch.
// ---------------------------------------------------------------------------
__global__ void lora_vectors_kernel(const float* __restrict__ sA,
                                    const float* __restrict__ sB,
                                    const float* __restrict__ hA,
                                    const float* __restrict__ hB) {
    int i = blockIdx.x * blockDim.x + threadIdx.x;
    if (i >= N) return;
    float4 a_s = *(const float4*)(sA + i * RANK);   // A[i, 0..3]
    float4 a_h = *(const float4*)(hA + i * RANK);
    float s = a_s.x * sB[0 * N + i] + a_s.y * sB[1 * N + i]
            + a_s.z * sB[2 * N + i] + a_s.w * sB[3 * N + i];
    float h = a_h.x * hB[0 * N + i] + a_h.y * hB[1 * N + i]
            + a_h.z * hB[2 * N + i] + a_h.w * hB[3 * N + i];
    g_scale[i] = s * SCALING;
    g_shift[i] = h * SCALING;
}

// ---------------------------------------------------------------------------
// Kernel 2: fused LayerNorm. One CTA per row; row held in registers so x is
// read from HBM exactly once. Streams 512 MiB total -> HBM-bound.
// ---------------------------------------------------------------------------
__global__ __launch_bounds__(TPB) void lora_ln_kernel(const float* __restrict__ x,
                                                      float* __restrict__ out) {
    const int t = threadIdx.x;
    const size_t row_off = (size_t)blockIdx.x * N;
    const float4* __restrict__ xr = (const float4*)(x + row_off);
    float4* __restrict__ yr = (float4*)(out + row_off);

    // Front-batched coalesced loads: thread t takes float4 slots t and t+TPB.
    float4 v[V_PER_T];
#pragma unroll
    for (int i = 0; i < V_PER_T; i++) v[i] = xr[t + i * TPB];

    float sum = 0.f, sq = 0.f;
#pragma unroll
    for (int i = 0; i < V_PER_T; i++) {
        sum += v[i].x + v[i].y + v[i].z + v[i].w;
        sq  += v[i].x * v[i].x + v[i].y * v[i].y
             + v[i].z * v[i].z + v[i].w * v[i].w;
    }

    // Warp tree reduction.
#pragma unroll
    for (int off = 16; off > 0; off >>= 1) {
        sum += __shfl_xor_sync(0xFFFFFFFFu, sum, off);
        sq  += __shfl_xor_sync(0xFFFFFFFFu, sq,  off);
    }

    __shared__ float s_sum[32], s_sq[32];
    __shared__ float s_mean, s_rstd;
    const int lane = t & 31, warp = t >> 5;
    if (lane == 0) { s_sum[warp] = sum; s_sq[warp] = sq; }
    __syncthreads();
    if (warp == 0) {
        float a = s_sum[lane], b = s_sq[lane];
#pragma unroll
        for (int off = 16; off > 0; off >>= 1) {
            a += __shfl_xor_sync(0xFFFFFFFFu, a, off);
            b += __shfl_xor_sync(0xFFFFFFFFu, b, off);
        }
        if (lane == 0) {
            float mean = a * (1.0f / N);
            float var  = b * (1.0f / N) - mean * mean;
            s_mean = mean;
            s_rstd = rsqrtf(var + EPS);
        }
    }
    __syncthreads();
    const float mean = s_mean, rstd = s_rstd;

    const float4* __restrict__ sc = (const float4*)g_scale;
    const float4* __restrict__ sh = (const float4*)g_shift;
#pragma unroll
    for (int i = 0; i < V_PER_T; i++) {
        const int idx = t + i * TPB;
        float4 s = sc[idx];
        float4 h = sh[idx];
        float4 o;
        o.x = (v[i].x - mean) * rstd * s.x + h.x;
        o.y = (v[i].y - mean) * rstd * s.y + h.y;
        o.z = (v[i].z - mean) * rstd * s.z + h.z;
        o.w = (v[i].w - mean) * rstd * s.w + h.w;
        yr[idx] = o;
    }
}

extern "C" void kernel_launch(void* const* d_in, const int* in_sizes, int n_in,
                              void* d_out, int out_size) {
    const float* x  = (const float*)d_in[0];
    const float* sA = (const float*)d_in[1];
    const float* sB = (const float*)d_in[2];
    const float* hA = (const float*)d_in[3];
    const float* hB = (const float*)d_in[4];
    float* out = (float*)d_out;

    const int rows = out_size / N;   // 8192

    lora_vectors_kernel<<<N / 256, 256>>>(sA, sB, hA, hB);
    lora_ln_kernel<<<rows, TPB>>>(x, out);
}